// round 3
// baseline (speedup 1.0000x reference)
#include <cuda_runtime.h>

// DyDepthwiseConvAtten: B=1024, N=100, C=256, K=3  (rows = 102400)
// Round 3: one warp handles 4 consecutive rows; Ww/gamma/beta/bw loaded into
// registers ONCE per warp (amortized 4x). Streaming cache hints on q/v/out.
// All reductions via shfl.xor; no shared memory, no barriers.

#define C_DIM 256
#define LN_EPS 1e-5f
#define WARPS_PER_CTA 8
#define RPW 4                  // rows per warp

__global__ __launch_bounds__(WARPS_PER_CTA * 32)
void dydw_atten_kernel(const float* __restrict__ q,
                       const float* __restrict__ v,
                       const float* __restrict__ Ww,   // [3,256]
                       const float* __restrict__ bw,   // [3]
                       const float* __restrict__ gamma,
                       const float* __restrict__ beta,
                       float* __restrict__ out) {
    const int lane = threadIdx.x & 31;
    const int wrp  = threadIdx.x >> 5;
    const int gwarp = blockIdx.x * WARPS_PER_CTA + wrp;
    const size_t row0 = (size_t)gwarp * RPW;            // first of 4 rows
    const int coff = lane * 8;                          // channel offset

    // ---- invariant loads: once per warp, live in registers across 4 rows ----
    const float4 w00 = *(const float4*)(Ww + coff);
    const float4 w01 = *(const float4*)(Ww + coff + 4);
    const float4 w10 = *(const float4*)(Ww + C_DIM + coff);
    const float4 w11 = *(const float4*)(Ww + C_DIM + coff + 4);
    const float4 w20 = *(const float4*)(Ww + 2 * C_DIM + coff);
    const float4 w21 = *(const float4*)(Ww + 2 * C_DIM + coff + 4);
    const float4 g0  = *(const float4*)(gamma + coff);
    const float4 g1  = *(const float4*)(gamma + coff + 4);
    const float4 b0  = *(const float4*)(beta  + coff);
    const float4 b1  = *(const float4*)(beta  + coff + 4);
    const float bw0 = bw[0], bw1 = bw[1], bw2 = bw[2];

    #pragma unroll
    for (int r = 0; r < RPW; r++) {
        const size_t base = (row0 + r) * C_DIM + coff;

        // streaming loads (evict-first: touched exactly once)
        const float4 q0 = __ldcs((const float4*)(q + base));
        const float4 q1 = __ldcs((const float4*)(q + base + 4));
        const float4 v0 = __ldcs((const float4*)(v + base));
        const float4 v1 = __ldcs((const float4*)(v + base + 4));

        // ---- dynamic weights: 3 dots over C, warp butterfly ----
        float p0 = q0.x*w00.x + q0.y*w00.y + q0.z*w00.z + q0.w*w00.w
                 + q1.x*w01.x + q1.y*w01.y + q1.z*w01.z + q1.w*w01.w;
        float p1 = q0.x*w10.x + q0.y*w10.y + q0.z*w10.z + q0.w*w10.w
                 + q1.x*w11.x + q1.y*w11.y + q1.z*w11.z + q1.w*w11.w;
        float p2 = q0.x*w20.x + q0.y*w20.y + q0.z*w20.z + q0.w*w20.w
                 + q1.x*w21.x + q1.y*w21.y + q1.z*w21.z + q1.w*w21.w;
        #pragma unroll
        for (int off = 16; off > 0; off >>= 1) {
            p0 += __shfl_xor_sync(0xffffffffu, p0, off);
            p1 += __shfl_xor_sync(0xffffffffu, p1, off);
            p2 += __shfl_xor_sync(0xffffffffu, p2, off);
        }
        const float kw0 = p0 + bw0;
        const float kw1 = p1 + bw1;
        const float kw2 = p2 + bw2;

        // ---- conv halos from neighbor lanes (zero-pad at row edges) ----
        float left  = __shfl_up_sync  (0xffffffffu, v1.w, 1);
        float right = __shfl_down_sync(0xffffffffu, v0.x, 1);
        if (lane == 0)  left  = 0.0f;
        if (lane == 31) right = 0.0f;

        float vv[10];
        vv[0]=left;  vv[1]=v0.x; vv[2]=v0.y; vv[3]=v0.z; vv[4]=v0.w;
        vv[5]=v1.x;  vv[6]=v1.y; vv[7]=v1.z; vv[8]=v1.w; vv[9]=right;

        float o[8];
        #pragma unroll
        for (int i = 0; i < 8; i++)
            o[i] = vv[i]*kw0 + vv[i+1]*kw1 + vv[i+2]*kw2;

        // ---- LayerNorm: fused sum + sumsq butterflies ----
        float s1 = 0.0f, s2 = 0.0f;
        #pragma unroll
        for (int i = 0; i < 8; i++) { s1 += o[i]; s2 += o[i]*o[i]; }
        #pragma unroll
        for (int off = 16; off > 0; off >>= 1) {
            s1 += __shfl_xor_sync(0xffffffffu, s1, off);
            s2 += __shfl_xor_sync(0xffffffffu, s2, off);
        }
        const float mu   = s1 * (1.0f / C_DIM);
        const float var  = s2 * (1.0f / C_DIM) - mu * mu;
        const float rstd = rsqrtf(var + LN_EPS);

        float4 r0f, r1f;
        r0f.x = (o[0]-mu)*rstd*g0.x + b0.x;
        r0f.y = (o[1]-mu)*rstd*g0.y + b0.y;
        r0f.z = (o[2]-mu)*rstd*g0.z + b0.z;
        r0f.w = (o[3]-mu)*rstd*g0.w + b0.w;
        r1f.x = (o[4]-mu)*rstd*g1.x + b1.x;
        r1f.y = (o[5]-mu)*rstd*g1.y + b1.y;
        r1f.z = (o[6]-mu)*rstd*g1.z + b1.z;
        r1f.w = (o[7]-mu)*rstd*g1.w + b1.w;

        __stcs((float4*)(out + base),     r0f);
        __stcs((float4*)(out + base + 4), r1f);
    }
}

extern "C" void kernel_launch(void* const* d_in, const int* in_sizes, int n_in,
                              void* d_out, int out_size) {
    const float* q     = (const float*)d_in[0];
    const float* v     = (const float*)d_in[1];
    const float* Ww    = (const float*)d_in[2];
    const float* bw    = (const float*)d_in[3];
    const float* gamma = (const float*)d_in[4];
    const float* beta  = (const float*)d_in[5];
    float* out = (float*)d_out;

    const int rows  = out_size / C_DIM;                      // 102400
    const int warps = rows / RPW;                            // 25600
    const int ctas  = warps / WARPS_PER_CTA;                 // 3200
    dydw_atten_kernel<<<ctas, WARPS_PER_CTA * 32>>>(q, v, Ww, bw, gamma, beta, out);
}